// round 1
// baseline (speedup 1.0000x reference)
#include <cuda_runtime.h>

// DEMA over x[B=32, T=4096, C=512], scan along T.
//   s_t = a*x_t + (1-a)*(s_{t-1} + b_{t-1})
//   b_t = B*(s_t - s_{t-1}) + (1-B)*b_{t-1}
//     == a*B*x_t - a*B*s_{t-1} + (1-a*B)*b_{t-1}   (shorter dependence chain)
// Linear recurrence with spectral radius sqrt(1-a)=0.8367 -> chunk the time
// axis with a warm-up halo; initial-state error decays to ~4e-8 after 96 steps.

#define B_DIM 32
#define T_DIM 4096
#define C_DIM 512
#define CHUNK 256
#define HALO  96
#define NCHUNK (T_DIM / CHUNK)   // 16

#define ALPHA 0.3f
#define BETA  0.1f

__device__ __forceinline__ void dema_step(float (&s)[4], float (&g)[4], const float4 xv) {
    const float OMA  = 1.0f - ALPHA;           // 0.7
    const float AB   = ALPHA * BETA;           // 0.03
    const float OMAB = 1.0f - ALPHA * BETA;    // 0.97
    float xs[4] = {xv.x, xv.y, xv.z, xv.w};
#pragma unroll
    for (int i = 0; i < 4; i++) {
        float ax   = ALPHA * xs[i];                               // off critical path
        float t1   = fmaf(AB, xs[i], OMAB * g[i]);                // b-chain: mul+fma
        float snew = fmaf(OMA, s[i] + g[i], ax);                  // s-chain: add+fma
        float gnew = fmaf(-AB, s[i], t1);                         // + old s
        s[i] = snew;
        g[i] = gnew;
    }
}

__global__ __launch_bounds__(128, 8)
void dema_kernel(const float* __restrict__ x, float* __restrict__ out) {
    const int bid = blockIdx.x;
    const int ci  = bid % NCHUNK;          // time chunk
    const int b   = bid / NCHUNK;          // batch
    const int c4  = threadIdx.x;           // float4 lane: channels [4*c4, 4*c4+3]

    const size_t base = (size_t)b * T_DIM * C_DIM + 4 * c4;
    const float4* __restrict__ xp = (const float4*)(x + base);
    float4* __restrict__       op = (float4*)(out + base);
    const int S = C_DIM / 4;               // float4 stride per time step = 128

    float s[4], g[4];
    const int t0   = ci * CHUNK;
    const int tend = t0 + CHUNK;
    int t;

    if (ci == 0) {
        // exact init: s0 = x[0], b0 = x[1]-x[0]; out[0] = s0
        float4 v0 = xp[0];
        float4 v1 = xp[S];
        s[0] = v0.x; s[1] = v0.y; s[2] = v0.z; s[3] = v0.w;
        g[0] = v1.x - v0.x; g[1] = v1.y - v0.y;
        g[2] = v1.z - v0.z; g[3] = v1.w - v0.w;
        op[0] = v0;
        t = 1;
    } else {
        // cold start HALO steps early; state error decays ~0.8367^HALO ≈ 4e-8
        const int tw = t0 - HALO;
        float4 v0 = xp[(size_t)tw * S];
        float4 v1 = xp[(size_t)(tw + 1) * S];
        s[0] = v0.x; s[1] = v0.y; s[2] = v0.z; s[3] = v0.w;
        g[0] = v1.x - v0.x; g[1] = v1.y - v0.y;
        g[2] = v1.z - v0.z; g[3] = v1.w - v0.w;
        t = tw + 1;
    }

    // software-pipelined: xv holds x[t]
    float4 xv = xp[(size_t)t * S];

    // warm-up (no stores) — only runs for ci > 0
    for (; t < t0; t++) {
        float4 xn = xp[(size_t)(t + 1) * S];
        dema_step(s, g, xv);
        xv = xn;
    }

    // main body: compute + store out[t] = s_t
    for (; t < tend; t++) {
        int tn = t + 1;
        if (tn >= T_DIM) tn = T_DIM - 1;       // clamp prefetch at the very end
        float4 xn = xp[(size_t)tn * S];
        dema_step(s, g, xv);
        op[(size_t)t * S] = make_float4(s[0], s[1], s[2], s[3]);
        xv = xn;
    }
}

extern "C" void kernel_launch(void* const* d_in, const int* in_sizes, int n_in,
                              void* d_out, int out_size) {
    const float* x = (const float*)d_in[0];
    float* out = (float*)d_out;
    dim3 grid(B_DIM * NCHUNK);   // 512 blocks
    dim3 block(128);             // 128 threads x 4 channels = 512 channels
    dema_kernel<<<grid, block>>>(x, out);
}

// round 3
// speedup vs baseline: 1.0818x; 1.0818x over previous
#include <cuda_runtime.h>

// DEMA over x[B=32, T=4096, C=512], scan along T.
//   s_t = a*x_t + (1-a)*(s_{t-1} + b_{t-1})
//   b_t = a*B*x_t - a*B*s_{t-1} + (1-a*B)*b_{t-1}
// Spectral radius sqrt(1-a)=0.8367 -> time-chunked with warm-up halo.
// HALO=64: initial-state error decays by 0.7^32 ~ 1.1e-5 (threshold 1e-3).
// Unroll-by-4 + 4-deep float4 prefetch: ~2KB in flight per warp so the
// chip holds ~4MB outstanding (Little's law needs ~2.5MB for 8TB/s).

#define B_DIM 32
#define T_DIM 4096
#define C_DIM 512
#define CHUNK 256
#define HALO  64
#define NCHUNK (T_DIM / CHUNK)   // 16

#define ALPHA 0.3f
#define BETA  0.1f

__device__ __forceinline__ void dema_step(float (&s)[4], float (&g)[4], const float4 xv) {
    const float OMA  = 1.0f - ALPHA;           // 0.7
    const float AB   = ALPHA * BETA;           // 0.03
    const float OMAB = 1.0f - ALPHA * BETA;    // 0.97
    float xs[4] = {xv.x, xv.y, xv.z, xv.w};
#pragma unroll
    for (int i = 0; i < 4; i++) {
        float ax   = ALPHA * xs[i];                 // off critical path
        float t1   = fmaf(AB, xs[i], OMAB * g[i]);  // b-chain
        float snew = fmaf(OMA, s[i] + g[i], ax);    // s-chain
        float gnew = fmaf(-AB, s[i], t1);
        s[i] = snew;
        g[i] = gnew;
    }
}

__global__ __launch_bounds__(128, 4)
void dema_kernel(const float* __restrict__ x, float* __restrict__ out) {
    const int bid = blockIdx.x;
    const int ci  = bid % NCHUNK;          // time chunk
    const int b   = bid / NCHUNK;          // batch
    const int c4  = threadIdx.x;           // float4 lane

    const size_t base = (size_t)b * T_DIM * C_DIM + 4 * c4;
    const float4* __restrict__ xp = (const float4*)(x + base);
    float4* __restrict__       op = (float4*)(out + base);
    const int S = C_DIM / 4;               // 128 float4 per time step

    const int t0    = ci * CHUNK;
    const int tend  = t0 + CHUNK;
    const int tinit = (ci == 0) ? 0 : (t0 - HALO);

    // init state from x[tinit], x[tinit+1]
    float4 v0 = xp[(size_t)tinit * S];
    float4 v1 = xp[(size_t)(tinit + 1) * S];
    float s[4] = {v0.x, v0.y, v0.z, v0.w};
    float g[4] = {v1.x - v0.x, v1.y - v0.y, v1.z - v0.z, v1.w - v0.w};
    if (ci == 0) op[0] = v0;               // out[0] = s0 = x[0] (exact)

    int t = tinit + 1;                     // first step to compute

    // prefetch window: xv[k] = x[t+k]
    float4 xv[4];
    xv[0] = v1;
#pragma unroll
    for (int k = 1; k < 4; k++) xv[k] = xp[(size_t)(t + k) * S];

    // main unrolled loop: load next 4, compute 4, store (predicated on body)
    for (; t + 3 < tend; t += 4) {
        float4 xn[4];
#pragma unroll
        for (int k = 0; k < 4; k++) {
            int tn = t + 4 + k;
            if (tn >= T_DIM) tn = T_DIM - 1;     // clamp at sequence end
            xn[k] = xp[(size_t)tn * S];
        }
#pragma unroll
        for (int k = 0; k < 4; k++) {
            dema_step(s, g, xv[k]);
            if (t + k >= t0)
                __stcs(&op[(size_t)(t + k) * S],
                       make_float4(s[0], s[1], s[2], s[3]));
            xv[k] = xn[k];
        }
    }

    // epilogue (<=3 steps); xv[k] already holds x[t..]
#pragma unroll
    for (int k = 0; k < 3 && t < tend; t++, k++) {
        dema_step(s, g, xv[k]);
        __stcs(&op[(size_t)t * S], make_float4(s[0], s[1], s[2], s[3]));
    }
}

extern "C" void kernel_launch(void* const* d_in, const int* in_sizes, int n_in,
                              void* d_out, int out_size) {
    const float* x = (const float*)d_in[0];
    float* out = (float*)d_out;
    dim3 grid(B_DIM * NCHUNK);   // 512 blocks
    dim3 block(128);
    dema_kernel<<<grid, block>>>(x, out);
}

// round 4
// speedup vs baseline: 1.0884x; 1.0061x over previous
#include <cuda_runtime.h>

// DEMA over x[B=32, T=4096, C=512], scan along T.
//   s_t = a*x_t + (1-a)*(s_{t-1} + b_{t-1})
//   b_t = a*B*x_t - a*B*s_{t-1} + (1-a*B)*b_{t-1}
// Spectral radius sqrt(1-a)=0.8367 -> time-chunked with warm-up halo.
// HALO=64: initial-state error ~0.7^32 ≈ 1.1e-5 (measured rel_err 4.4e-5,
// threshold 1e-3). CHUNK=128 -> 1024 blocks: doubles chip-wide in-flight
// bytes (Little's law) to push achieved HBM BW from 5.5 toward 7 TB/s.

#define B_DIM 32
#define T_DIM 4096
#define C_DIM 512
#define CHUNK 128
#define HALO  64
#define NCHUNK (T_DIM / CHUNK)   // 32

#define ALPHA 0.3f
#define BETA  0.1f

__device__ __forceinline__ void dema_step(float (&s)[4], float (&g)[4], const float4 xv) {
    const float OMA  = 1.0f - ALPHA;           // 0.7
    const float AB   = ALPHA * BETA;           // 0.03
    const float OMAB = 1.0f - ALPHA * BETA;    // 0.97
    float xs[4] = {xv.x, xv.y, xv.z, xv.w};
#pragma unroll
    for (int i = 0; i < 4; i++) {
        float ax   = ALPHA * xs[i];                 // off critical path
        float t1   = fmaf(AB, xs[i], OMAB * g[i]);  // b-chain
        float snew = fmaf(OMA, s[i] + g[i], ax);    // s-chain
        float gnew = fmaf(-AB, s[i], t1);
        s[i] = snew;
        g[i] = gnew;
    }
}

__global__ __launch_bounds__(128, 8)
void dema_kernel(const float* __restrict__ x, float* __restrict__ out) {
    const int bid = blockIdx.x;
    const int ci  = bid % NCHUNK;          // time chunk
    const int b   = bid / NCHUNK;          // batch
    const int c4  = threadIdx.x;           // float4 lane

    const size_t base = (size_t)b * T_DIM * C_DIM + 4 * c4;
    const float4* __restrict__ xp = (const float4*)(x + base);
    float4* __restrict__       op = (float4*)(out + base);
    const int S = C_DIM / 4;               // 128 float4 per time step

    const int t0    = ci * CHUNK;
    const int tend  = t0 + CHUNK;
    const int tinit = (ci == 0) ? 0 : (t0 - HALO);

    // init state from x[tinit], x[tinit+1]
    float4 v0 = xp[(size_t)tinit * S];
    float4 v1 = xp[(size_t)(tinit + 1) * S];
    float s[4] = {v0.x, v0.y, v0.z, v0.w};
    float g[4] = {v1.x - v0.x, v1.y - v0.y, v1.z - v0.z, v1.w - v0.w};
    if (ci == 0) op[0] = v0;               // out[0] = s0 = x[0] (exact)

    int t = tinit + 1;                     // first step to compute

    // prefetch window: xv[k] = x[t+k]
    float4 xv[4];
    xv[0] = v1;
#pragma unroll
    for (int k = 1; k < 4; k++) xv[k] = xp[(size_t)(t + k) * S];

    // main unrolled loop: load next 4, compute 4, store (predicated on body)
    for (; t + 3 < tend; t += 4) {
        float4 xn[4];
#pragma unroll
        for (int k = 0; k < 4; k++) {
            int tn = t + 4 + k;
            tn = (tn >= T_DIM) ? (T_DIM - 1) : tn;   // clamp at sequence end
            xn[k] = xp[(size_t)tn * S];
        }
#pragma unroll
        for (int k = 0; k < 4; k++) {
            dema_step(s, g, xv[k]);
            if (t + k >= t0)
                __stcs(&op[(size_t)(t + k) * S],
                       make_float4(s[0], s[1], s[2], s[3]));
            xv[k] = xn[k];
        }
    }

    // epilogue (<=3 steps); xv[k] already holds x[t..]
#pragma unroll
    for (int k = 0; k < 3 && t < tend; t++, k++) {
        dema_step(s, g, xv[k]);
        __stcs(&op[(size_t)t * S], make_float4(s[0], s[1], s[2], s[3]));
    }
}

extern "C" void kernel_launch(void* const* d_in, const int* in_sizes, int n_in,
                              void* d_out, int out_size) {
    const float* x = (const float*)d_in[0];
    float* out = (float*)d_out;
    dim3 grid(B_DIM * NCHUNK);   // 1024 blocks
    dim3 block(128);
    dema_kernel<<<grid, block>>>(x, out);
}

// round 5
// speedup vs baseline: 1.1610x; 1.0667x over previous
#include <cuda_runtime.h>

// DEMA over x[B=32, T=4096, C=512], scan along T.
//   s_t = a*x_t + (1-a)*(s_{t-1} + b_{t-1})
//   b_t = a*B*x_t - a*B*s_{t-1} + (1-a*B)*b_{t-1}
// Time-chunked with warm-up halo (spectral radius sqrt(0.7)=0.8367;
// HALO=64 -> state error ~1e-5, threshold 1e-3).
// CHUNK=256 keeps halo overhead at 25% (traffic 576 MB); float2 lanes give
// 512 blocks x 8 warps = 4096 warps (the concurrency that measured 6.2 TB/s
// in R4); prefetch depth 8 keeps 64 B/thread in flight (Little's law).

#define B_DIM 32
#define T_DIM 4096
#define C_DIM 512
#define CHUNK 256
#define HALO  64
#define NCHUNK (T_DIM / CHUNK)   // 16
#define THREADS 256              // float2 lanes: 256*2 = 512 channels
#define PF 8                     // prefetch depth

#define ALPHA 0.3f
#define BETA  0.1f

__device__ __forceinline__ void dema_step(float (&s)[2], float (&g)[2], const float2 xv) {
    const float OMA  = 1.0f - ALPHA;           // 0.7
    const float AB   = ALPHA * BETA;           // 0.03
    const float OMAB = 1.0f - ALPHA * BETA;    // 0.97
    float xs[2] = {xv.x, xv.y};
#pragma unroll
    for (int i = 0; i < 2; i++) {
        float ax   = ALPHA * xs[i];                 // off critical path
        float t1   = fmaf(AB, xs[i], OMAB * g[i]);  // b-chain
        float snew = fmaf(OMA, s[i] + g[i], ax);    // s-chain
        float gnew = fmaf(-AB, s[i], t1);
        s[i] = snew;
        g[i] = gnew;
    }
}

__global__ __launch_bounds__(THREADS, 4)
void dema_kernel(const float* __restrict__ x, float* __restrict__ out) {
    const int bid = blockIdx.x;
    const int ci  = bid % NCHUNK;          // time chunk
    const int b   = bid / NCHUNK;          // batch
    const int c2  = threadIdx.x;           // float2 lane

    const size_t base = (size_t)b * T_DIM * C_DIM + 2 * c2;
    const float2* __restrict__ xp = (const float2*)(x + base);
    float2* __restrict__       op = (float2*)(out + base);
    const int S = C_DIM / 2;               // 256 float2 per time step

    const int t0    = ci * CHUNK;
    const int tend  = t0 + CHUNK;
    const int tinit = (ci == 0) ? 0 : (t0 - HALO);

    // init state from x[tinit], x[tinit+1]
    float2 v0 = xp[(size_t)tinit * S];
    float2 v1 = xp[(size_t)(tinit + 1) * S];
    float s[2] = {v0.x, v0.y};
    float g[2] = {v1.x - v0.x, v1.y - v0.y};
    if (ci == 0) op[0] = v0;               // out[0] = s0 = x[0] (exact)

    int t = tinit + 1;                     // first step to compute

    // prefetch window: xv[k] = x[t+k]
    float2 xv[PF];
    xv[0] = v1;
#pragma unroll
    for (int k = 1; k < PF; k++) xv[k] = xp[(size_t)(t + k) * S];

    // main unrolled loop: load next PF, compute PF, store (predicated on body)
    for (; t + (PF - 1) < tend; t += PF) {
        float2 xn[PF];
#pragma unroll
        for (int k = 0; k < PF; k++) {
            int tn = t + PF + k;
            tn = (tn >= T_DIM) ? (T_DIM - 1) : tn;   // clamp at sequence end
            xn[k] = xp[(size_t)tn * S];
        }
#pragma unroll
        for (int k = 0; k < PF; k++) {
            dema_step(s, g, xv[k]);
            if (t + k >= t0)
                __stcs(&op[(size_t)(t + k) * S], make_float2(s[0], s[1]));
            xv[k] = xn[k];
        }
    }

    // epilogue (<= PF-1 steps); xv[k] already holds x[t..]
#pragma unroll
    for (int k = 0; k < PF - 1 && t < tend; t++, k++) {
        dema_step(s, g, xv[k]);
        __stcs(&op[(size_t)t * S], make_float2(s[0], s[1]));
    }
}

extern "C" void kernel_launch(void* const* d_in, const int* in_sizes, int n_in,
                              void* d_out, int out_size) {
    const float* x = (const float*)d_in[0];
    float* out = (float*)d_out;
    dim3 grid(B_DIM * NCHUNK);   // 512 blocks x 8 warps = 4096 warps
    dim3 block(THREADS);
    dema_kernel<<<grid, block>>>(x, out);
}

// round 7
// speedup vs baseline: 1.1980x; 1.0319x over previous
#include <cuda_runtime.h>

// DEMA over x[B=32, T=4096, C=512], scan along T.
//   s_t = a*x_t + (1-a)*(s_{t-1} + b_{t-1})
//   b_t = a*B*x_t - a*B*s_{t-1} + (1-a*B)*b_{t-1}
// Time-chunked with warm-up halo (spectral radius sqrt(0.7)=0.8367;
// HALO=64 -> state error ~1e-5, threshold 1e-3).
//
// Traffic plan (R5 showed we sit on the traffic/BW floor at ~6.1 TB/s):
//  - halo loads (first toucher of those lines) use DEFAULT policy -> retained
//    in L2 so the neighboring block's late body-tail reads HIT (-63 MB DRAM).
//  - body loads use __ldcs (evict-first; single-use or second-use-hit).
//  - stores use __stcs (never re-read).

#define B_DIM 32
#define T_DIM 4096
#define C_DIM 512
#define CHUNK 256
#define HALO  64
#define NCHUNK (T_DIM / CHUNK)   // 16
#define THREADS 256              // float2 lanes: 256*2 = 512 channels
#define PF 8                     // prefetch depth

#define ALPHA 0.3f
#define BETA  0.1f

__device__ __forceinline__ void dema_step(float (&s)[2], float (&g)[2], const float2 xv) {
    const float OMA  = 1.0f - ALPHA;           // 0.7
    const float AB   = ALPHA * BETA;           // 0.03
    const float OMAB = 1.0f - ALPHA * BETA;    // 0.97
    float xs[2] = {xv.x, xv.y};
#pragma unroll
    for (int i = 0; i < 2; i++) {
        float ax   = ALPHA * xs[i];                 // off critical path
        float t1   = fmaf(AB, xs[i], OMAB * g[i]);  // b-chain
        float snew = fmaf(OMA, s[i] + g[i], ax);    // s-chain
        float gnew = fmaf(-AB, s[i], t1);
        s[i] = snew;
        g[i] = gnew;
    }
}

__global__ __launch_bounds__(THREADS, 4)
void dema_kernel(const float* __restrict__ x, float* __restrict__ out) {
    const int bid = blockIdx.x;
    const int ci  = bid % NCHUNK;          // time chunk
    const int b   = bid / NCHUNK;          // batch
    const int c2  = threadIdx.x;           // float2 lane

    const size_t base = (size_t)b * T_DIM * C_DIM + 2 * c2;
    const float2* __restrict__ xp = (const float2*)(x + base);
    float2* __restrict__       op = (float2*)(out + base);
    const int S = C_DIM / 2;               // 256 float2 per time step

    const int t0    = ci * CHUNK;
    const int tend  = t0 + CHUNK;
    const int tinit = (ci == 0) ? 0 : (t0 - HALO);

    // init state from x[tinit], x[tinit+1] (halo region: cached loads)
    float2 v0 = xp[(size_t)tinit * S];
    float2 v1 = xp[(size_t)(tinit + 1) * S];
    float s[2] = {v0.x, v0.y};
    float g[2] = {v1.x - v0.x, v1.y - v0.y};
    if (ci == 0) op[0] = v0;               // out[0] = s0 = x[0] (exact)

    int t = tinit + 1;                     // first step to compute

    // prefetch window: xv[k] = x[t+k] (still halo region -> cached)
    float2 xv[PF];
    xv[0] = v1;
#pragma unroll
    for (int k = 1; k < PF; k++) xv[k] = xp[(size_t)(t + k) * S];

    // Phase A: warm-up iterations whose LOADS (t+PF..t+2PF-1) are all < t0.
    // Default (cached) loads so these lines are retained in L2 for the
    // neighboring block's body-tail reads. No stores here (t+k < t0).
    for (; t + 2 * PF - 1 < t0; t += PF) {
        float2 xn[PF];
#pragma unroll
        for (int k = 0; k < PF; k++)
            xn[k] = xp[(size_t)(t + PF + k) * S];
#pragma unroll
        for (int k = 0; k < PF; k++) {
            dema_step(s, g, xv[k]);
            xv[k] = xn[k];
        }
    }

    // Phase B: remaining warm-up + body. Streaming loads (__ldcs), streaming
    // stores (__stcs), store predicated on t+k >= t0.
    for (; t + PF - 1 < tend; t += PF) {
        float2 xn[PF];
#pragma unroll
        for (int k = 0; k < PF; k++) {
            int tn = t + PF + k;
            tn = (tn >= T_DIM) ? (T_DIM - 1) : tn;   // clamp at sequence end
            xn[k] = __ldcs(&xp[(size_t)tn * S]);
        }
#pragma unroll
        for (int k = 0; k < PF; k++) {
            dema_step(s, g, xv[k]);
            if (t + k >= t0)
                __stcs(&op[(size_t)(t + k) * S], make_float2(s[0], s[1]));
            xv[k] = xn[k];
        }
    }

    // epilogue (<= PF-1 steps); xv[k] already holds x[t..]
#pragma unroll
    for (int k = 0; k < PF - 1 && t < tend; t++, k++) {
        dema_step(s, g, xv[k]);
        __stcs(&op[(size_t)t * S], make_float2(s[0], s[1]));
    }
}

extern "C" void kernel_launch(void* const* d_in, const int* in_sizes, int n_in,
                              void* d_out, int out_size) {
    const float* x = (const float*)d_in[0];
    float* out = (float*)d_out;
    dim3 grid(B_DIM * NCHUNK);   // 512 blocks x 8 warps = 4096 warps
    dim3 block(THREADS);
    dema_kernel<<<grid, block>>>(x, out);
}